// round 1
// baseline (speedup 1.0000x reference)
#include <cuda_runtime.h>
#include <cstdint>
#include <math.h>

// Problem constants
#define NT   2048   // tokens
#define NH   2048   // hidden dim
#define NI   5632   // intermediate dim
#define NEXP 4      // topk_ids % 4  -> only experts 0..3 are ever active
#define NTOPK 2

typedef unsigned long long u64;

// ---------------- device scratch (static: no allocations allowed) ----------
__device__ int   g_cnt[NEXP];
__device__ int   g_tok[NEXP * NT];
__device__ float g_wgt[NEXP * NT];
// gathered activation buffer: [expert][position][I]  (4*2048*5632 f32 = 184.5 MB)
__device__ float g_act[(size_t)NEXP * NT * NI];

// ---------------- packed f32x2 helpers (Blackwell FFMA2 path) --------------
__device__ __forceinline__ u64 pk2(float lo, float hi) {
  u64 r; asm("mov.b64 %0, {%1, %2};" : "=l"(r) : "f"(lo), "f"(hi)); return r;
}
__device__ __forceinline__ float2 upk2(u64 v) {
  float2 f; asm("mov.b64 {%0, %1}, %2;" : "=f"(f.x), "=f"(f.y) : "l"(v)); return f;
}
#define FMA2(d, a, b) asm("fma.rn.f32x2 %0, %1, %2, %0;" : "+l"(d) : "l"(a), "l"(b))

// ---------------- kernel 0: zero the per-expert counters -------------------
__global__ void zero_cnt_kernel() {
  if (threadIdx.x < NEXP) g_cnt[threadIdx.x] = 0;
}

// ---------------- kernel 1: routing / compaction ----------------------------
// route[e,t] = sum_k (topk_ids[t,k] % 4 == e) * topk_weights[t,k]
__global__ void route_kernel(const int* __restrict__ ids,
                             const float* __restrict__ tw) {
  int t = blockIdx.x * blockDim.x + threadIdx.x;
  if (t >= NT) return;
  int e0 = ids[t * NTOPK + 0] & 3;
  int e1 = ids[t * NTOPK + 1] & 3;
  float w0 = tw[t * NTOPK + 0];
  float w1 = tw[t * NTOPK + 1];
  if (e0 == e1) {
    int p = atomicAdd(&g_cnt[e0], 1);
    g_tok[e0 * NT + p] = t;
    g_wgt[e0 * NT + p] = w0 + w1;
  } else {
    int p0 = atomicAdd(&g_cnt[e0], 1);
    g_tok[e0 * NT + p0] = t;
    g_wgt[e0 * NT + p0] = w0;
    int p1 = atomicAdd(&g_cnt[e1], 1);
    g_tok[e1 * NT + p1] = t;
    g_wgt[e1 * NT + p1] = w1;
  }
}

// ---------------- kernel 2: gathered GEMM1 + SiLU*gate ---------------------
// For expert e: act[pos, i] = silu(X[pos] . w1[i]) * (X[pos] . w3[i])
// Tile: M=128 (positions), N=64 (i), Kstep=16.  256 threads, 8x4 per thread
// with rows split (tr*4) and (64+tr*4). Packed f32x2 accumulators.
__global__ __launch_bounds__(256, 2) void gemm1_act_kernel(
    const float* __restrict__ hidden, const float* __restrict__ w13) {
  const int e   = blockIdx.z;
  const int cnt = g_cnt[e];
  const int m0  = blockIdx.y * 128;
  if (m0 >= cnt) return;
  const int n0 = blockIdx.x * 64;

  __shared__ float As[16][128];
  __shared__ float B1s[16][64];
  __shared__ float B3s[16][64];
  __shared__ int   toks[128];

  const int tx = threadIdx.x;
  if (tx < 128) {
    int m = m0 + tx;
    toks[tx] = g_tok[e * NT + (m < cnt ? m : (cnt - 1))];
  }
  __syncthreads();

  const int tc = tx & 15;   // 16 col groups * 4 cols
  const int tr = tx >> 4;   // 16 row groups; rows tr*4..+3 and 64+tr*4..+3

  u64 c1[4][4], c3[4][4];
#pragma unroll
  for (int i = 0; i < 4; ++i)
#pragma unroll
    for (int j = 0; j < 4; ++j) { c1[i][j] = 0ULL; c3[i][j] = 0ULL; }

  const int kk0   = (tx & 3) * 4;   // k offset this thread loads
  const int arow0 = tx >> 2;        // 0..63
  const int arow1 = arow0 + 64;     // 64..127
  const int brow  = tx >> 2;        // 0..63

  const size_t h0base = (size_t)toks[arow0] * NH + kk0;
  const size_t h1base = (size_t)toks[arow1] * NH + kk0;
  const size_t w1base = ((size_t)e * (2 * NI) + (n0 + brow)) * NH + kk0;
  const size_t w3base = ((size_t)e * (2 * NI) + (NI + n0 + brow)) * NH + kk0;

  for (int kb = 0; kb < NH; kb += 16) {
    float4 v0 = *(const float4*)&hidden[h0base + kb];
    float4 v1 = *(const float4*)&hidden[h1base + kb];
    float4 b1 = *(const float4*)&w13[w1base + kb];
    float4 b3 = *(const float4*)&w13[w3base + kb];

    As[kk0 + 0][arow0] = v0.x; As[kk0 + 1][arow0] = v0.y;
    As[kk0 + 2][arow0] = v0.z; As[kk0 + 3][arow0] = v0.w;
    As[kk0 + 0][arow1] = v1.x; As[kk0 + 1][arow1] = v1.y;
    As[kk0 + 2][arow1] = v1.z; As[kk0 + 3][arow1] = v1.w;
    B1s[kk0 + 0][brow] = b1.x; B1s[kk0 + 1][brow] = b1.y;
    B1s[kk0 + 2][brow] = b1.z; B1s[kk0 + 3][brow] = b1.w;
    B3s[kk0 + 0][brow] = b3.x; B3s[kk0 + 1][brow] = b3.y;
    B3s[kk0 + 2][brow] = b3.z; B3s[kk0 + 3][brow] = b3.w;
    __syncthreads();

#pragma unroll
    for (int kk = 0; kk < 16; ++kk) {
      float4 a0 = *(const float4*)&As[kk][tr * 4];
      float4 a1 = *(const float4*)&As[kk][64 + tr * 4];
      float4 f1 = *(const float4*)&B1s[kk][tc * 4];
      float4 f3 = *(const float4*)&B3s[kk][tc * 4];
      u64 ap[4]  = { pk2(a0.x, a0.y), pk2(a0.z, a0.w),
                     pk2(a1.x, a1.y), pk2(a1.z, a1.w) };
      u64 bp1[4] = { pk2(f1.x, f1.x), pk2(f1.y, f1.y),
                     pk2(f1.z, f1.z), pk2(f1.w, f1.w) };
      u64 bp3[4] = { pk2(f3.x, f3.x), pk2(f3.y, f3.y),
                     pk2(f3.z, f3.z), pk2(f3.w, f3.w) };
#pragma unroll
      for (int i = 0; i < 4; ++i)
#pragma unroll
        for (int j = 0; j < 4; ++j) {
          FMA2(c1[i][j], ap[i], bp1[j]);
          FMA2(c3[i][j], ap[i], bp3[j]);
        }
    }
    __syncthreads();
  }

  // epilogue: act = silu(g1) * g3
#pragma unroll
  for (int i = 0; i < 4; ++i) {
    const int rbase = (i < 2) ? (tr * 4 + i * 2) : (64 + tr * 4 + (i - 2) * 2);
#pragma unroll
    for (int j = 0; j < 4; ++j) {
      float2 g1 = upk2(c1[i][j]);
      float2 g3 = upk2(c3[i][j]);
      float a0 = (g1.x / (1.0f + expf(-g1.x))) * g3.x;
      float a1 = (g1.y / (1.0f + expf(-g1.y))) * g3.y;
      const int col = n0 + tc * 4 + j;
      const int mA = m0 + rbase, mB = mA + 1;
      if (mA < cnt) g_act[((size_t)e * NT + mA) * NI + col] = a0;
      if (mB < cnt) g_act[((size_t)e * NT + mB) * NI + col] = a1;
    }
  }
}

// ---------------- kernel 3: gathered GEMM2 + weighted scatter --------------
// out[t, h] += route_w * ( act[pos] . w2[e][h] )
__global__ __launch_bounds__(256, 2) void gemm2_scatter_kernel(
    const float* __restrict__ w2, float* __restrict__ out) {
  const int e   = blockIdx.z;
  const int cnt = g_cnt[e];
  const int m0  = blockIdx.y * 128;
  if (m0 >= cnt) return;
  const int n0 = blockIdx.x * 64;   // h dim

  __shared__ float As[16][128];
  __shared__ float Bs[16][64];
  __shared__ int   toks[128];
  __shared__ float wgts[128];

  const int tx = threadIdx.x;
  if (tx < 128) {
    int m  = m0 + tx;
    int mc = m < cnt ? m : (cnt - 1);
    toks[tx] = g_tok[e * NT + mc];
    wgts[tx] = g_wgt[e * NT + mc];
  }
  __syncthreads();

  const int tc = tx & 15;
  const int tr = tx >> 4;

  u64 cc[4][4];
#pragma unroll
  for (int i = 0; i < 4; ++i)
#pragma unroll
    for (int j = 0; j < 4; ++j) cc[i][j] = 0ULL;

  const int kk0   = (tx & 3) * 4;
  const int arow0 = tx >> 2;
  const int arow1 = arow0 + 64;
  const int brow  = tx >> 2;

  // rows >= cnt contain stale-but-finite data; results for them are discarded
  const size_t abase0 = ((size_t)e * NT + (m0 + arow0)) * NI + kk0;
  const size_t abase1 = ((size_t)e * NT + (m0 + arow1)) * NI + kk0;
  const size_t wbase  = ((size_t)e * NH + (n0 + brow)) * NI + kk0;

  for (int kb = 0; kb < NI; kb += 16) {
    float4 v0 = *(const float4*)&g_act[abase0 + kb];
    float4 v1 = *(const float4*)&g_act[abase1 + kb];
    float4 bv = *(const float4*)&w2[wbase + kb];

    As[kk0 + 0][arow0] = v0.x; As[kk0 + 1][arow0] = v0.y;
    As[kk0 + 2][arow0] = v0.z; As[kk0 + 3][arow0] = v0.w;
    As[kk0 + 0][arow1] = v1.x; As[kk0 + 1][arow1] = v1.y;
    As[kk0 + 2][arow1] = v1.z; As[kk0 + 3][arow1] = v1.w;
    Bs[kk0 + 0][brow] = bv.x; Bs[kk0 + 1][brow] = bv.y;
    Bs[kk0 + 2][brow] = bv.z; Bs[kk0 + 3][brow] = bv.w;
    __syncthreads();

#pragma unroll
    for (int kk = 0; kk < 16; ++kk) {
      float4 a0 = *(const float4*)&As[kk][tr * 4];
      float4 a1 = *(const float4*)&As[kk][64 + tr * 4];
      float4 bb = *(const float4*)&Bs[kk][tc * 4];
      u64 ap[4] = { pk2(a0.x, a0.y), pk2(a0.z, a0.w),
                    pk2(a1.x, a1.y), pk2(a1.z, a1.w) };
      u64 bp[4] = { pk2(bb.x, bb.x), pk2(bb.y, bb.y),
                    pk2(bb.z, bb.z), pk2(bb.w, bb.w) };
#pragma unroll
      for (int i = 0; i < 4; ++i)
#pragma unroll
        for (int j = 0; j < 4; ++j) FMA2(cc[i][j], ap[i], bp[j]);
    }
    __syncthreads();
  }

#pragma unroll
  for (int i = 0; i < 4; ++i) {
    const int rbase = (i < 2) ? (tr * 4 + i * 2) : (64 + tr * 4 + (i - 2) * 2);
#pragma unroll
    for (int j = 0; j < 4; ++j) {
      float2 v = upk2(cc[i][j]);
      const int col = n0 + tc * 4 + j;
      const int mA = m0 + rbase, mB = mA + 1;
      if (mA < cnt)
        atomicAdd(&out[(size_t)toks[rbase] * NH + col], wgts[rbase] * v.x);
      if (mB < cnt)
        atomicAdd(&out[(size_t)toks[rbase + 1] * NH + col], wgts[rbase + 1] * v.y);
    }
  }
}

// ---------------- launcher --------------------------------------------------
extern "C" void kernel_launch(void* const* d_in, const int* in_sizes, int n_in,
                              void* d_out, int out_size) {
  const float* hidden = (const float*)d_in[0];            // (T, H) f32
  const float* w13    = (const float*)d_in[1];            // (E, 2I, H) f32
  const float* w2     = (const float*)d_in[2];            // (E, H, I) f32
  const float* tw     = (const float*)d_in[3];            // (T, K) f32
  const int*   ids    = (const int*)d_in[4];              // (T, K) i32
  float*       out    = (float*)d_out;                    // (T, H) f32
  (void)in_sizes; (void)n_in;

  cudaMemsetAsync(out, 0, (size_t)out_size * sizeof(float), 0);
  zero_cnt_kernel<<<1, 32>>>();
  route_kernel<<<(NT + 255) / 256, 256>>>(ids, tw);
  gemm1_act_kernel<<<dim3(NI / 64, NT / 128, NEXP), 256>>>(hidden, w13);
  gemm2_scatter_kernel<<<dim3(NH / 64, NT / 128, NEXP), 256>>>(w2, out);
}

// round 3
// speedup vs baseline: 5.2333x; 5.2333x over previous
#include <cuda_runtime.h>
#include <cstdint>
#include <math.h>

// Problem constants
#define NT   2048
#define NH   2048
#define NI   5632
#define NEXP 4
#define NTOPK 2

#define BM 128
#define BN 256
#define BK 32
#define ASTRIDE 36          // padded float stride: conflict-free for frag LDS + STS.128
#define THREADS 512

// ---------------- device scratch ----------------
__device__ int   g_cnt[NEXP];
__device__ int   g_tok[NEXP * NT];
__device__ float g_wgt[NEXP * NT];
__device__ float g_act[(size_t)NEXP * NT * NI];

// ---------------- shared layout ----------------
struct SMem {
  float A[2][BM * ASTRIDE];   // 2 x 18KB
  float B[2][BN * ASTRIDE];   // 2 x 36KB
  int   toks[BM];
  float wgts[BM];
};
#define SMEM_BYTES ((int)sizeof(SMem))

// ---------------- helpers ----------------
__device__ __forceinline__ uint32_t f2tf(float f) {
  uint32_t r; asm("cvt.rna.tf32.f32 %0, %1;" : "=r"(r) : "f"(f)); return r;
}
__device__ __forceinline__ uint4 cvt4(float4 v) {
  uint4 u; u.x = f2tf(v.x); u.y = f2tf(v.y); u.z = f2tf(v.z); u.w = f2tf(v.w); return u;
}
__device__ __forceinline__ void mma8(float* c, const uint32_t* a, const uint32_t* b) {
  asm volatile(
      "mma.sync.aligned.m16n8k8.row.col.f32.tf32.tf32.f32 "
      "{%0,%1,%2,%3}, {%4,%5,%6,%7}, {%8,%9}, {%0,%1,%2,%3};"
      : "+f"(c[0]), "+f"(c[1]), "+f"(c[2]), "+f"(c[3])
      : "r"(a[0]), "r"(a[1]), "r"(a[2]), "r"(a[3]), "r"(b[0]), "r"(b[1]));
}
__device__ __forceinline__ uint32_t fbits(float f) { return __float_as_uint(f); }

// ---------------- routing ----------------
__global__ void zero_cnt_kernel() {
  if (threadIdx.x < NEXP) g_cnt[threadIdx.x] = 0;
}
__global__ void route_kernel(const int* __restrict__ ids, const float* __restrict__ tw) {
  int t = blockIdx.x * blockDim.x + threadIdx.x;
  if (t >= NT) return;
  int e0 = ids[t * NTOPK + 0] & 3;
  int e1 = ids[t * NTOPK + 1] & 3;
  float w0 = tw[t * NTOPK + 0], w1 = tw[t * NTOPK + 1];
  if (e0 == e1) {
    int p = atomicAdd(&g_cnt[e0], 1);
    g_tok[e0 * NT + p] = t; g_wgt[e0 * NT + p] = w0 + w1;
  } else {
    int p0 = atomicAdd(&g_cnt[e0], 1);
    g_tok[e0 * NT + p0] = t; g_wgt[e0 * NT + p0] = w0;
    int p1 = atomicAdd(&g_cnt[e1], 1);
    g_tok[e1 * NT + p1] = t; g_wgt[e1 * NT + p1] = w1;
  }
}

// fragment LDS + MMA for one buffer (BK=32 -> 4 k8 steps)
__device__ __forceinline__ void compute_tile(const float* __restrict__ As,
                                             const float* __restrict__ Bs,
                                             float acc[2][8][4],
                                             int wM, int wN, int gid, int tg) {
#pragma unroll
  for (int k8 = 0; k8 < 4; ++k8) {
    const int kk = k8 * 8;
    uint32_t a[2][4], b[8][2];
#pragma unroll
    for (int mt = 0; mt < 2; ++mt) {
      const int base = (wM * 32 + mt * 16 + gid) * ASTRIDE + kk + tg;
      a[mt][0] = fbits(As[base]);
      a[mt][1] = fbits(As[base + 8 * ASTRIDE]);
      a[mt][2] = fbits(As[base + 4]);
      a[mt][3] = fbits(As[base + 8 * ASTRIDE + 4]);
    }
#pragma unroll
    for (int nt = 0; nt < 8; ++nt) {
      const int base = (wN * 64 + nt * 8 + gid) * ASTRIDE + kk + tg;
      b[nt][0] = fbits(Bs[base]);
      b[nt][1] = fbits(Bs[base + 4]);
    }
#pragma unroll
    for (int mt = 0; mt < 2; ++mt)
#pragma unroll
      for (int nt = 0; nt < 8; ++nt)
        mma8(acc[mt][nt], a[mt], b[nt]);
  }
}

// ---------------- GEMM1 + fused SiLU*gate -----------------------------------
// B tile rows interleaved: row 2j = W1[n0+j], row 2j+1 = W3[n0+j]  (j in 0..127)
// => thread's (c0,c1) = (g1, g3) for the same output column i.
__global__ __launch_bounds__(THREADS, 1) void gemm1_tc(const float* __restrict__ hidden,
                                                       const float* __restrict__ w13) {
  const int e   = blockIdx.z;
  const int cnt = g_cnt[e];
  const int m0  = blockIdx.y * BM;
  if (m0 >= cnt) return;
  const int n0 = blockIdx.x * 128;   // i-tile (128 columns of I)

  extern __shared__ char smraw[];
  SMem& sm = *(SMem*)smraw;
  const int tid = threadIdx.x;

  if (tid < BM) {
    int m = m0 + tid;
    sm.toks[tid] = g_tok[e * NT + (m < cnt ? m : cnt - 1)];
  }
  __syncthreads();

  // loader setup: thread -> (row = tid/8 [+64/128/192], quad = tid%8)
  const int lr = tid >> 3;      // 0..63
  const int lq = tid & 7;       // 0..7
  const float* asrc0 = hidden + (size_t)sm.toks[lr]      * NH + lq * 4;
  const float* asrc1 = hidden + (size_t)sm.toks[64 + lr] * NH + lq * 4;
  const float* bsrc[4];
#pragma unroll
  for (int p = 0; p < 4; ++p) {
    const int r = lr + p * 64;            // smem B row
    const int j = r >> 1, half = r & 1;   // interleave: even=W1, odd=W3
    bsrc[p] = w13 + ((size_t)e * 2 * NI + (size_t)half * NI + (n0 + j)) * NH + lq * 4;
  }

  const int lane = tid & 31, warp = tid >> 5;
  const int wM = warp & 3, wN = warp >> 2;
  const int gid = lane >> 2, tg = lane & 3;

  float acc[2][8][4];
#pragma unroll
  for (int mt = 0; mt < 2; ++mt)
#pragma unroll
    for (int nt = 0; nt < 8; ++nt)
#pragma unroll
      for (int q = 0; q < 4; ++q) acc[mt][nt][q] = 0.0f;

  const int KB = NH / BK;   // 64
  float4 pa0, pa1, pb[4];

  // prologue: stage 0
  pa0 = *(const float4*)(asrc0);
  pa1 = *(const float4*)(asrc1);
#pragma unroll
  for (int p = 0; p < 4; ++p) pb[p] = *(const float4*)(bsrc[p]);
  *(uint4*)&sm.A[0][lr * ASTRIDE + lq * 4]        = cvt4(pa0);
  *(uint4*)&sm.A[0][(64 + lr) * ASTRIDE + lq * 4] = cvt4(pa1);
#pragma unroll
  for (int p = 0; p < 4; ++p)
    *(uint4*)&sm.B[0][(lr + p * 64) * ASTRIDE + lq * 4] = cvt4(pb[p]);
  __syncthreads();

  for (int kb = 0; kb < KB; ++kb) {
    const int buf = kb & 1;
    if (kb + 1 < KB) {
      const int ko = (kb + 1) * BK;
      pa0 = *(const float4*)(asrc0 + ko);
      pa1 = *(const float4*)(asrc1 + ko);
#pragma unroll
      for (int p = 0; p < 4; ++p) pb[p] = *(const float4*)(bsrc[p] + ko);
    }
    compute_tile(sm.A[buf], sm.B[buf], acc, wM, wN, gid, tg);
    if (kb + 1 < KB) {
      const int nb = buf ^ 1;
      *(uint4*)&sm.A[nb][lr * ASTRIDE + lq * 4]        = cvt4(pa0);
      *(uint4*)&sm.A[nb][(64 + lr) * ASTRIDE + lq * 4] = cvt4(pa1);
#pragma unroll
      for (int p = 0; p < 4; ++p)
        *(uint4*)&sm.B[nb][(lr + p * 64) * ASTRIDE + lq * 4] = cvt4(pb[p]);
    }
    __syncthreads();
  }

  // epilogue: act = silu(g1)*g3
#pragma unroll
  for (int mt = 0; mt < 2; ++mt) {
    const int mrow0 = m0 + wM * 32 + mt * 16 + gid;
    const int mrow1 = mrow0 + 8;
#pragma unroll
    for (int nt = 0; nt < 8; ++nt) {
      const int i = n0 + wN * 32 + nt * 4 + tg;
      float g1 = acc[mt][nt][0], g3 = acc[mt][nt][1];
      float a0 = g1 / (1.0f + __expf(-g1)) * g3;
      g1 = acc[mt][nt][2]; g3 = acc[mt][nt][3];
      float a1 = g1 / (1.0f + __expf(-g1)) * g3;
      if (mrow0 < cnt) g_act[((size_t)e * NT + mrow0) * NI + i] = a0;
      if (mrow1 < cnt) g_act[((size_t)e * NT + mrow1) * NI + i] = a1;
    }
  }
}

// ---------------- GEMM2 + weighted scatter -----------------------------------
__global__ __launch_bounds__(THREADS, 1) void gemm2_tc(const float* __restrict__ w2,
                                                       float* __restrict__ out) {
  const int e   = blockIdx.z;
  const int cnt = g_cnt[e];
  const int m0  = blockIdx.y * BM;
  if (m0 >= cnt) return;
  const int n0 = blockIdx.x * BN;    // h-tile (256 columns of H)

  extern __shared__ char smraw[];
  SMem& sm = *(SMem*)smraw;
  const int tid = threadIdx.x;

  if (tid < BM) {
    int m = m0 + tid;
    int mc = m < cnt ? m : cnt - 1;
    sm.toks[tid] = g_tok[e * NT + mc];
    sm.wgts[tid] = g_wgt[e * NT + mc];
  }
  __syncthreads();

  const int lr = tid >> 3;
  const int lq = tid & 7;
  const int mA0 = m0 + lr      < cnt ? m0 + lr      : cnt - 1;
  const int mA1 = m0 + 64 + lr < cnt ? m0 + 64 + lr : cnt - 1;
  const float* asrc0 = g_act + ((size_t)e * NT + mA0) * NI + lq * 4;
  const float* asrc1 = g_act + ((size_t)e * NT + mA1) * NI + lq * 4;
  const float* bsrc[4];
#pragma unroll
  for (int p = 0; p < 4; ++p)
    bsrc[p] = w2 + ((size_t)e * NH + (n0 + lr + p * 64)) * NI + lq * 4;

  const int lane = tid & 31, warp = tid >> 5;
  const int wM = warp & 3, wN = warp >> 2;
  const int gid = lane >> 2, tg = lane & 3;

  float acc[2][8][4];
#pragma unroll
  for (int mt = 0; mt < 2; ++mt)
#pragma unroll
    for (int nt = 0; nt < 8; ++nt)
#pragma unroll
      for (int q = 0; q < 4; ++q) acc[mt][nt][q] = 0.0f;

  const int KB = NI / BK;   // 176
  float4 pa0, pa1, pb[4];

  pa0 = *(const float4*)(asrc0);
  pa1 = *(const float4*)(asrc1);
#pragma unroll
  for (int p = 0; p < 4; ++p) pb[p] = *(const float4*)(bsrc[p]);
  *(uint4*)&sm.A[0][lr * ASTRIDE + lq * 4]        = cvt4(pa0);
  *(uint4*)&sm.A[0][(64 + lr) * ASTRIDE + lq * 4] = cvt4(pa1);
#pragma unroll
  for (int p = 0; p < 4; ++p)
    *(uint4*)&sm.B[0][(lr + p * 64) * ASTRIDE + lq * 4] = cvt4(pb[p]);
  __syncthreads();

  for (int kb = 0; kb < KB; ++kb) {
    const int buf = kb & 1;
    if (kb + 1 < KB) {
      const int ko = (kb + 1) * BK;
      pa0 = *(const float4*)(asrc0 + ko);
      pa1 = *(const float4*)(asrc1 + ko);
#pragma unroll
      for (int p = 0; p < 4; ++p) pb[p] = *(const float4*)(bsrc[p] + ko);
    }
    compute_tile(sm.A[buf], sm.B[buf], acc, wM, wN, gid, tg);
    if (kb + 1 < KB) {
      const int nb = buf ^ 1;
      *(uint4*)&sm.A[nb][lr * ASTRIDE + lq * 4]        = cvt4(pa0);
      *(uint4*)&sm.A[nb][(64 + lr) * ASTRIDE + lq * 4] = cvt4(pa1);
#pragma unroll
      for (int p = 0; p < 4; ++p)
        *(uint4*)&sm.B[nb][(lr + p * 64) * ASTRIDE + lq * 4] = cvt4(pb[p]);
    }
    __syncthreads();
  }

  // epilogue: out[tok, h] += wgt * acc
#pragma unroll
  for (int mt = 0; mt < 2; ++mt) {
    const int lr0 = wM * 32 + mt * 16 + gid;   // local row in tile
    const int lr1 = lr0 + 8;
    const bool v0 = (m0 + lr0) < cnt;
    const bool v1 = (m0 + lr1) < cnt;
    const int   t0 = sm.toks[lr0], t1 = sm.toks[lr1];
    const float w0 = sm.wgts[lr0], w1 = sm.wgts[lr1];
#pragma unroll
    for (int nt = 0; nt < 8; ++nt) {
      const int h = n0 + wN * 64 + nt * 8 + 2 * tg;
      if (v0) {
        atomicAdd(&out[(size_t)t0 * NH + h],     w0 * acc[mt][nt][0]);
        atomicAdd(&out[(size_t)t0 * NH + h + 1], w0 * acc[mt][nt][1]);
      }
      if (v1) {
        atomicAdd(&out[(size_t)t1 * NH + h],     w1 * acc[mt][nt][2]);
        atomicAdd(&out[(size_t)t1 * NH + h + 1], w1 * acc[mt][nt][3]);
      }
    }
  }
}

// ---------------- launcher ----------------
extern "C" void kernel_launch(void* const* d_in, const int* in_sizes, int n_in,
                              void* d_out, int out_size) {
  const float* hidden = (const float*)d_in[0];
  const float* w13    = (const float*)d_in[1];
  const float* w2     = (const float*)d_in[2];
  const float* tw     = (const float*)d_in[3];
  const int*   ids    = (const int*)d_in[4];
  float*       out    = (float*)d_out;
  (void)in_sizes; (void)n_in;

  cudaFuncSetAttribute(gemm1_tc, cudaFuncAttributeMaxDynamicSharedMemorySize, SMEM_BYTES);
  cudaFuncSetAttribute(gemm2_tc, cudaFuncAttributeMaxDynamicSharedMemorySize, SMEM_BYTES);

  cudaMemsetAsync(out, 0, (size_t)out_size * sizeof(float), 0);
  zero_cnt_kernel<<<1, 32>>>();
  route_kernel<<<(NT + 255) / 256, 256>>>(ids, tw);
  gemm1_tc<<<dim3(NI / 128, NT / BM, NEXP), THREADS, SMEM_BYTES>>>(hidden, w13);
  gemm2_tc<<<dim3(NH / BN, NT / BM, NEXP), THREADS, SMEM_BYTES>>>(w2, out);
}

// round 4
// speedup vs baseline: 5.7305x; 1.0950x over previous
#include <cuda_runtime.h>
#include <cstdint>
#include <math.h>

// Problem constants
#define NT   2048
#define NH   2048
#define NI   5632
#define NEXP 4
#define NTOPK 2

#define BM 128
#define BN 256
#define BK 32
#define ASTRIDE 36          // padded float stride: conflict-free for LDSM + STS.128
#define THREADS 512

// ---------------- device scratch ----------------
__device__ int   g_cnt[NEXP];
__device__ int   g_tok[NEXP * NT];
__device__ float g_wgt[NEXP * NT];
__device__ float g_act[(size_t)NEXP * NT * NI];

// ---------------- shared layout ----------------
struct SMem {
  float A[2][BM * ASTRIDE];   // 2 x 18KB
  float B[2][BN * ASTRIDE];   // 2 x 36KB
  int   toks[BM];
  float wgts[BM];
};
#define SMEM_BYTES ((int)sizeof(SMem))
#define ABUF_BYTES (BM * ASTRIDE * 4)
#define BBUF_BYTES (BN * ASTRIDE * 4)

// ---------------- helpers ----------------
__device__ __forceinline__ uint32_t smem_u32(const void* p) {
  uint32_t a;
  asm("{ .reg .u64 t; cvta.to.shared.u64 t, %1; cvt.u32.u64 %0, t; }" : "=r"(a) : "l"(p));
  return a;
}
__device__ __forceinline__ uint32_t f2tf(float f) {
  uint32_t r; asm("cvt.rna.tf32.f32 %0, %1;" : "=r"(r) : "f"(f)); return r;
}
__device__ __forceinline__ uint4 cvt4(float4 v) {
  uint4 u; u.x = f2tf(v.x); u.y = f2tf(v.y); u.z = f2tf(v.z); u.w = f2tf(v.w); return u;
}
__device__ __forceinline__ void mma8(float* c, const uint32_t* a, const uint32_t* b) {
  asm volatile(
      "mma.sync.aligned.m16n8k8.row.col.f32.tf32.tf32.f32 "
      "{%0,%1,%2,%3}, {%4,%5,%6,%7}, {%8,%9}, {%0,%1,%2,%3};"
      : "+f"(c[0]), "+f"(c[1]), "+f"(c[2]), "+f"(c[3])
      : "r"(a[0]), "r"(a[1]), "r"(a[2]), "r"(a[3]), "r"(b[0]), "r"(b[1]));
}
__device__ __forceinline__ void ldsm4(uint32_t r[4], uint32_t addr) {
  asm volatile("ldmatrix.sync.aligned.m8n8.x4.shared.b16 {%0,%1,%2,%3}, [%4];"
               : "=r"(r[0]), "=r"(r[1]), "=r"(r[2]), "=r"(r[3]) : "r"(addr));
}

// ---------------- routing ----------------
__global__ void zero_cnt_kernel() {
  if (threadIdx.x < NEXP) g_cnt[threadIdx.x] = 0;
}
__global__ void route_kernel(const int* __restrict__ ids, const float* __restrict__ tw) {
  int t = blockIdx.x * blockDim.x + threadIdx.x;
  if (t >= NT) return;
  int e0 = ids[t * NTOPK + 0] & 3;
  int e1 = ids[t * NTOPK + 1] & 3;
  float w0 = tw[t * NTOPK + 0], w1 = tw[t * NTOPK + 1];
  if (e0 == e1) {
    int p = atomicAdd(&g_cnt[e0], 1);
    g_tok[e0 * NT + p] = t; g_wgt[e0 * NT + p] = w0 + w1;
  } else {
    int p0 = atomicAdd(&g_cnt[e0], 1);
    g_tok[e0 * NT + p0] = t; g_wgt[e0 * NT + p0] = w0;
    int p1 = atomicAdd(&g_cnt[e1], 1);
    g_tok[e1 * NT + p1] = t; g_wgt[e1 * NT + p1] = w1;
  }
}

// ---------------- fragment compute: LDSM.x4 + m16n8k8 -----------------------
// A frag matrices per mt: (rows 0-7,k0-3),(rows 8-15,k0-3),(rows 0-7,k4-7),(rows 8-15,k4-7)
// B frag matrices per pair p: (n 0-7,k0-3),(n 0-7,k4-7),(n 8-15,k0-3),(n 8-15,k4-7)
__device__ __forceinline__ void compute_tile(uint32_t aA0, uint32_t aA1,
                                             const uint32_t* bA, uint32_t boff,
                                             float acc[2][8][4]) {
#pragma unroll
  for (int k8 = 0; k8 < 4; ++k8) {
    uint32_t a[2][4], b[4][4];
    ldsm4(a[0], aA0 + k8 * 32);
    ldsm4(a[1], aA1 + k8 * 32);
#pragma unroll
    for (int p = 0; p < 4; ++p) ldsm4(b[p], bA[p] + boff + k8 * 32);
#pragma unroll
    for (int mt = 0; mt < 2; ++mt)
#pragma unroll
      for (int p = 0; p < 4; ++p) {
        mma8(acc[mt][2 * p],     a[mt], &b[p][0]);
        mma8(acc[mt][2 * p + 1], a[mt], &b[p][2]);
      }
  }
}

// ---------------- GEMM1 + fused SiLU*gate -----------------------------------
// B tile rows interleaved: row 2j = W1[n0+j], row 2j+1 = W3[n0+j]
__global__ __launch_bounds__(THREADS, 1) void gemm1_tc(const float* __restrict__ hidden,
                                                       const float* __restrict__ w13) {
  const int e   = blockIdx.z;
  const int cnt = g_cnt[e];
  const int m0  = blockIdx.y * BM;
  if (m0 >= cnt) return;
  const int n0 = blockIdx.x * 128;

  extern __shared__ char smraw[];
  SMem& sm = *(SMem*)smraw;
  const int tid = threadIdx.x;

  if (tid < BM) {
    int m = m0 + tid;
    sm.toks[tid] = g_tok[e * NT + (m < cnt ? m : cnt - 1)];
  }
  __syncthreads();

  const int lr = tid >> 3;
  const int lq = tid & 7;
  const float* asrc0 = hidden + (size_t)sm.toks[lr]      * NH + lq * 4;
  const float* asrc1 = hidden + (size_t)sm.toks[64 + lr] * NH + lq * 4;
  const float* bsrc[4];
#pragma unroll
  for (int p = 0; p < 4; ++p) {
    const int r = lr + p * 64;
    const int j = r >> 1, half = r & 1;
    bsrc[p] = w13 + ((size_t)e * 2 * NI + (size_t)half * NI + (n0 + j)) * NH + lq * 4;
  }

  const int lane = tid & 31, warp = tid >> 5;
  const int wM = warp & 3, wN = warp >> 2;
  const int gid = lane >> 2, tg = lane & 3;

  // LDSM source addresses (hoisted; conflict-free on ASTRIDE=36)
  const int L8 = lane & 7, q = lane >> 3;
  const uint32_t smA = smem_u32(&sm.A[0][0]);
  const uint32_t smB = smem_u32(&sm.B[0][0]);
  const uint32_t aAddr0 =
      smA + (uint32_t)(((wM * 32 + L8 + (q & 1) * 8) * ASTRIDE + (q >> 1) * 4) * 4);
  const uint32_t aAddr1 = aAddr0 + 16 * ASTRIDE * 4;
  uint32_t bAddr[4];
#pragma unroll
  for (int p = 0; p < 4; ++p)
    bAddr[p] = smB +
        (uint32_t)(((wN * 64 + p * 16 + (q >> 1) * 8 + L8) * ASTRIDE + (q & 1) * 4) * 4);

  float acc[2][8][4];
#pragma unroll
  for (int mt = 0; mt < 2; ++mt)
#pragma unroll
    for (int nt = 0; nt < 8; ++nt)
#pragma unroll
      for (int qq = 0; qq < 4; ++qq) acc[mt][nt][qq] = 0.0f;

  const int KB = NH / BK;   // 64
  float4 pa0, pa1, pb[4];

  pa0 = *(const float4*)(asrc0);
  pa1 = *(const float4*)(asrc1);
#pragma unroll
  for (int p = 0; p < 4; ++p) pb[p] = *(const float4*)(bsrc[p]);
  *(uint4*)&sm.A[0][lr * ASTRIDE + lq * 4]        = cvt4(pa0);
  *(uint4*)&sm.A[0][(64 + lr) * ASTRIDE + lq * 4] = cvt4(pa1);
#pragma unroll
  for (int p = 0; p < 4; ++p)
    *(uint4*)&sm.B[0][(lr + p * 64) * ASTRIDE + lq * 4] = cvt4(pb[p]);
  __syncthreads();

  for (int kb = 0; kb < KB; ++kb) {
    const int buf = kb & 1;
    if (kb + 1 < KB) {
      const int ko = (kb + 1) * BK;
      pa0 = *(const float4*)(asrc0 + ko);
      pa1 = *(const float4*)(asrc1 + ko);
#pragma unroll
      for (int p = 0; p < 4; ++p) pb[p] = *(const float4*)(bsrc[p] + ko);
    }
    compute_tile(aAddr0 + buf * ABUF_BYTES, aAddr1 + buf * ABUF_BYTES,
                 bAddr, buf * BBUF_BYTES, acc);
    if (kb + 1 < KB) {
      const int nb = buf ^ 1;
      *(uint4*)&sm.A[nb][lr * ASTRIDE + lq * 4]        = cvt4(pa0);
      *(uint4*)&sm.A[nb][(64 + lr) * ASTRIDE + lq * 4] = cvt4(pa1);
#pragma unroll
      for (int p = 0; p < 4; ++p)
        *(uint4*)&sm.B[nb][(lr + p * 64) * ASTRIDE + lq * 4] = cvt4(pb[p]);
    }
    __syncthreads();
  }

  // epilogue: act = silu(g1)*g3 (c0=g1, c1=g3 thanks to interleaved B rows)
#pragma unroll
  for (int mt = 0; mt < 2; ++mt) {
    const int mrow0 = m0 + wM * 32 + mt * 16 + gid;
    const int mrow1 = mrow0 + 8;
#pragma unroll
    for (int nt = 0; nt < 8; ++nt) {
      const int i = n0 + wN * 32 + nt * 4 + tg;
      float g1 = acc[mt][nt][0], g3 = acc[mt][nt][1];
      float a0 = g1 / (1.0f + __expf(-g1)) * g3;
      g1 = acc[mt][nt][2]; g3 = acc[mt][nt][3];
      float a1 = g1 / (1.0f + __expf(-g1)) * g3;
      if (mrow0 < cnt) g_act[((size_t)e * NT + mrow0) * NI + i] = a0;
      if (mrow1 < cnt) g_act[((size_t)e * NT + mrow1) * NI + i] = a1;
    }
  }
}

// ---------------- GEMM2 + weighted scatter -----------------------------------
__global__ __launch_bounds__(THREADS, 1) void gemm2_tc(const float* __restrict__ w2,
                                                       float* __restrict__ out) {
  const int e   = blockIdx.z;
  const int cnt = g_cnt[e];
  const int m0  = blockIdx.y * BM;
  if (m0 >= cnt) return;
  const int n0 = blockIdx.x * BN;

  extern __shared__ char smraw[];
  SMem& sm = *(SMem*)smraw;
  const int tid = threadIdx.x;

  if (tid < BM) {
    int m = m0 + tid;
    int mc = m < cnt ? m : cnt - 1;
    sm.toks[tid] = g_tok[e * NT + mc];
    sm.wgts[tid] = g_wgt[e * NT + mc];
  }
  __syncthreads();

  const int lr = tid >> 3;
  const int lq = tid & 7;
  const int mA0 = m0 + lr      < cnt ? m0 + lr      : cnt - 1;
  const int mA1 = m0 + 64 + lr < cnt ? m0 + 64 + lr : cnt - 1;
  const float* asrc0 = g_act + ((size_t)e * NT + mA0) * NI + lq * 4;
  const float* asrc1 = g_act + ((size_t)e * NT + mA1) * NI + lq * 4;
  const float* bsrc[4];
#pragma unroll
  for (int p = 0; p < 4; ++p)
    bsrc[p] = w2 + ((size_t)e * NH + (n0 + lr + p * 64)) * NI + lq * 4;

  const int lane = tid & 31, warp = tid >> 5;
  const int wM = warp & 3, wN = warp >> 2;
  const int gid = lane >> 2, tg = lane & 3;

  const int L8 = lane & 7, q = lane >> 3;
  const uint32_t smA = smem_u32(&sm.A[0][0]);
  const uint32_t smB = smem_u32(&sm.B[0][0]);
  const uint32_t aAddr0 =
      smA + (uint32_t)(((wM * 32 + L8 + (q & 1) * 8) * ASTRIDE + (q >> 1) * 4) * 4);
  const uint32_t aAddr1 = aAddr0 + 16 * ASTRIDE * 4;
  uint32_t bAddr[4];
#pragma unroll
  for (int p = 0; p < 4; ++p)
    bAddr[p] = smB +
        (uint32_t)(((wN * 64 + p * 16 + (q >> 1) * 8 + L8) * ASTRIDE + (q & 1) * 4) * 4);

  float acc[2][8][4];
#pragma unroll
  for (int mt = 0; mt < 2; ++mt)
#pragma unroll
    for (int nt = 0; nt < 8; ++nt)
#pragma unroll
      for (int qq = 0; qq < 4; ++qq) acc[mt][nt][qq] = 0.0f;

  const int KB = NI / BK;   // 176
  float4 pa0, pa1, pb[4];

  pa0 = *(const float4*)(asrc0);
  pa1 = *(const float4*)(asrc1);
#pragma unroll
  for (int p = 0; p < 4; ++p) pb[p] = *(const float4*)(bsrc[p]);
  *(uint4*)&sm.A[0][lr * ASTRIDE + lq * 4]        = cvt4(pa0);
  *(uint4*)&sm.A[0][(64 + lr) * ASTRIDE + lq * 4] = cvt4(pa1);
#pragma unroll
  for (int p = 0; p < 4; ++p)
    *(uint4*)&sm.B[0][(lr + p * 64) * ASTRIDE + lq * 4] = cvt4(pb[p]);
  __syncthreads();

  for (int kb = 0; kb < KB; ++kb) {
    const int buf = kb & 1;
    if (kb + 1 < KB) {
      const int ko = (kb + 1) * BK;
      pa0 = *(const float4*)(asrc0 + ko);
      pa1 = *(const float4*)(asrc1 + ko);
#pragma unroll
      for (int p = 0; p < 4; ++p) pb[p] = *(const float4*)(bsrc[p] + ko);
    }
    compute_tile(aAddr0 + buf * ABUF_BYTES, aAddr1 + buf * ABUF_BYTES,
                 bAddr, buf * BBUF_BYTES, acc);
    if (kb + 1 < KB) {
      const int nb = buf ^ 1;
      *(uint4*)&sm.A[nb][lr * ASTRIDE + lq * 4]        = cvt4(pa0);
      *(uint4*)&sm.A[nb][(64 + lr) * ASTRIDE + lq * 4] = cvt4(pa1);
#pragma unroll
      for (int p = 0; p < 4; ++p)
        *(uint4*)&sm.B[nb][(lr + p * 64) * ASTRIDE + lq * 4] = cvt4(pb[p]);
    }
    __syncthreads();
  }

  // epilogue: out[tok, h] += wgt * acc
#pragma unroll
  for (int mt = 0; mt < 2; ++mt) {
    const int lr0 = wM * 32 + mt * 16 + gid;
    const int lr1 = lr0 + 8;
    const bool v0 = (m0 + lr0) < cnt;
    const bool v1 = (m0 + lr1) < cnt;
    const int   t0 = sm.toks[lr0], t1 = sm.toks[lr1];
    const float w0 = sm.wgts[lr0], w1 = sm.wgts[lr1];
#pragma unroll
    for (int nt = 0; nt < 8; ++nt) {
      const int h = n0 + wN * 64 + nt * 8 + 2 * tg;
      if (v0) {
        atomicAdd(&out[(size_t)t0 * NH + h],     w0 * acc[mt][nt][0]);
        atomicAdd(&out[(size_t)t0 * NH + h + 1], w0 * acc[mt][nt][1]);
      }
      if (v1) {
        atomicAdd(&out[(size_t)t1 * NH + h],     w1 * acc[mt][nt][2]);
        atomicAdd(&out[(size_t)t1 * NH + h + 1], w1 * acc[mt][nt][3]);
      }
    }
  }
}

// ---------------- launcher ----------------
extern "C" void kernel_launch(void* const* d_in, const int* in_sizes, int n_in,
                              void* d_out, int out_size) {
  const float* hidden = (const float*)d_in[0];
  const float* w13    = (const float*)d_in[1];
  const float* w2     = (const float*)d_in[2];
  const float* tw     = (const float*)d_in[3];
  const int*   ids    = (const int*)d_in[4];
  float*       out    = (float*)d_out;
  (void)in_sizes; (void)n_in;

  cudaFuncSetAttribute(gemm1_tc, cudaFuncAttributeMaxDynamicSharedMemorySize, SMEM_BYTES);
  cudaFuncSetAttribute(gemm2_tc, cudaFuncAttributeMaxDynamicSharedMemorySize, SMEM_BYTES);

  cudaMemsetAsync(out, 0, (size_t)out_size * sizeof(float), 0);
  zero_cnt_kernel<<<1, 32>>>();
  route_kernel<<<(NT + 255) / 256, 256>>>(ids, tw);
  gemm1_tc<<<dim3(NI / 128, NT / BM, NEXP), THREADS, SMEM_BYTES>>>(hidden, w13);
  gemm2_tc<<<dim3(NH / BN, NT / BM, NEXP), THREADS, SMEM_BYTES>>>(w2, out);
}